// round 16
// baseline (speedup 1.0000x reference)
#include <cuda_runtime.h>
#include <math_constants.h>

// Problem constants (fixed: centers [8, 4096, 3] fp32)
#define BATCH    8
#define NPTS     4096
#define TOTPTS   (BATCH * NPTS)       // 32768
#define TPB      128                  // threads per block (min kernel)
#define IPT      4                    // i-points per thread
#define ITILE    (TPB * IPT)          // 512 i per block
#define NITILES  (NPTS / ITILE)       // 8
#define SSPLIT   32                   // j-splits
#define JT       (NPTS / SSPLIT)      // 128 j per block
#define NQ       (JT / 4)             // 32 quads
#define NBLK_MIN (BATCH * NITILES * SSPLIT)   // 2048
#define NPG      (TOTPTS / 4)         // 8192 float4 point-groups
#define CMB_BLKS 256
#define CMB_TPB  128
#define PG_PER_BLK 32                 // point-groups per combine block
#define TARGET_F 0.2f

// Scratch (static device globals — no allocation allowed).
// Partial mins in [split][point] layout: coalesced store AND float4 load. 4 MB.
// Fully overwritten every call -> no reset needed.
__device__ float g_pmin[SSPLIT * TOTPTS];
__device__ float g_partials[CMB_BLKS];
__device__ unsigned int g_sync;   // zero-init; self-resets each call

// ---- packed f32x2 helpers (FFMA2: only reachable via PTX) ----
__device__ __forceinline__ unsigned long long pack2(float a, float b) {
    unsigned long long r;
    asm("mov.b64 %0, {%1, %2};" : "=l"(r) : "f"(a), "f"(b));
    return r;
}
__device__ __forceinline__ unsigned long long fma2(unsigned long long a,
                                                   unsigned long long b,
                                                   unsigned long long c) {
    unsigned long long d;
    asm("fma.rn.f32x2 %0, %1, %2, %3;" : "=l"(d) : "l"(a), "l"(b), "l"(c));
    return d;
}
__device__ __forceinline__ float2 unpack2(unsigned long long v) {
    float2 f;
    asm("mov.b64 {%0, %1}, %2;" : "=f"(f.x), "=f"(f.y) : "l"(v));
    return f;
}
__device__ __forceinline__ float4 fmin4(float4 a, float4 b) {
    return make_float4(fminf(a.x, b.x), fminf(a.y, b.y),
                       fminf(a.z, b.z), fminf(a.w, b.w));
}

__global__ void __launch_bounds__(TPB)
nn_min_kernel(const float* __restrict__ centers)
{
    // SoA j-tile: LDS.128 per array yields pre-packed {j,j+1} f32x2 lanes
    __shared__ __align__(16) float spx[JT], spy[JT], spz[JT], spw[JT];

    const int blk = blockIdx.x;
    const int s   = blk & (SSPLIT - 1);            // j-split      0..31
    const int it  = (blk >> 5) & (NITILES - 1);    // i-tile       0..7
    const int b   = blk >> 8;                      // batch        0..7
    const int tid = threadIdx.x;

    const float* cb = centers + (size_t)b * NPTS * 3;
    const int j_lo  = s  * JT;
    const int i_lo  = it * ITILE;

    // Stage j-tile (128 points)
    for (int p = tid; p < JT; p += TPB) {
        float x = cb[3 * (j_lo + p) + 0];
        float y = cb[3 * (j_lo + p) + 1];
        float z = cb[3 * (j_lo + p) + 2];
        spx[p] = x; spy[p] = y; spz[p] = z;
        spw[p] = fmaf(x, x, fmaf(y, y, z * z));
    }

    // i-constants, pre-packed {c,c} once
    unsigned long long ax2[IPT], ay2[IPT], az2[IPT];
    float sqi[IPT], tminA[IPT], tminB[IPT];
    int   msel[IPT];   // local j index equal to this i (may be out of range)
    #pragma unroll
    for (int k = 0; k < IPT; ++k) {
        const int gi = i_lo + tid + k * TPB;
        float x = cb[3 * gi + 0];
        float y = cb[3 * gi + 1];
        float z = cb[3 * gi + 2];
        ax2[k] = pack2(-2.0f * x, -2.0f * x);
        ay2[k] = pack2(-2.0f * y, -2.0f * y);
        az2[k] = pack2(-2.0f * z, -2.0f * z);
        sqi[k] = fmaf(x, x, fmaf(y, y, z * z));
        tminA[k] = CUDART_INF_F;
        tminB[k] = CUDART_INF_F;
        msel[k] = gi - j_lo;
    }
    __syncthreads();

    const ulonglong2* px2 = (const ulonglong2*)spx;
    const ulonglong2* py2 = (const ulonglong2*)spy;
    const ulonglong2* pz2 = (const ulonglong2*)spz;
    const ulonglong2* pw2 = (const ulonglong2*)spw;

    // Explicit quad prefetch: batch-load next quad's 4 LDS.128 before math.
    ulonglong2 nx = px2[0], ny = py2[0], nz = pz2[0], nw = pw2[0];

    if ((s >> 2) != it) {
        // Off-diagonal block: clean fully-unrolled loop, no compares
        #pragma unroll
        for (int q = 0; q < NQ; ++q) {
            const ulonglong2 px = nx, py = ny, pz = nz, pw = nw;
            if (q + 1 < NQ) {
                nx = px2[q + 1]; ny = py2[q + 1];
                nz = pz2[q + 1]; nw = pw2[q + 1];
            }
            #pragma unroll
            for (int k = 0; k < IPT; ++k) {
                unsigned long long t0 = fma2(pz.x, az2[k], pw.x);
                t0 = fma2(py.x, ay2[k], t0);
                t0 = fma2(px.x, ax2[k], t0);
                unsigned long long t1 = fma2(pz.y, az2[k], pw.y);
                t1 = fma2(py.y, ay2[k], t1);
                t1 = fma2(px.y, ax2[k], t1);
                float2 a = unpack2(t0), c = unpack2(t1);
                tminA[k] = fminf(tminA[k], fminf(a.x, a.y));
                tminB[k] = fminf(tminB[k], fminf(c.x, c.y));
            }
        }
    } else {
        // Diagonal block (1/8 of blocks): predicate out j == i
        #pragma unroll
        for (int q = 0; q < NQ; ++q) {
            const int jb = q * 4;
            const ulonglong2 px = nx, py = ny, pz = nz, pw = nw;
            if (q + 1 < NQ) {
                nx = px2[q + 1]; ny = py2[q + 1];
                nz = pz2[q + 1]; nw = pw2[q + 1];
            }
            #pragma unroll
            for (int k = 0; k < IPT; ++k) {
                unsigned long long t0 = fma2(pz.x, az2[k], pw.x);
                t0 = fma2(py.x, ay2[k], t0);
                t0 = fma2(px.x, ax2[k], t0);
                unsigned long long t1 = fma2(pz.y, az2[k], pw.y);
                t1 = fma2(py.y, ay2[k], t1);
                t1 = fma2(px.y, ax2[k], t1);
                float2 a = unpack2(t0), c = unpack2(t1);
                const int m = msel[k];
                a.x = (jb + 0 == m) ? CUDART_INF_F : a.x;
                a.y = (jb + 1 == m) ? CUDART_INF_F : a.y;
                c.x = (jb + 2 == m) ? CUDART_INF_F : c.x;
                c.y = (jb + 3 == m) ? CUDART_INF_F : c.y;
                tminA[k] = fminf(tminA[k], fminf(a.x, a.y));
                tminB[k] = fminf(tminB[k], fminf(c.x, c.y));
            }
        }
    }

    // Coalesced partial store: pm[s][point]  (plain STG, no atomics)
    float* pm = g_pmin + (size_t)s * TOTPTS + b * NPTS + i_lo + tid;
    #pragma unroll
    for (int k = 0; k < IPT; ++k)
        pm[k * TPB] = sqi[k] + fminf(tminA[k], tminB[k]);
}

// Fused combine+final, MLP-by-construction.
// 256 blocks x 128 threads; thread = (point-group pidx, split-quarter qrt).
// 8 independent LDG.128 batch-loaded into separate registers, then tree-min.
// Cross-quarter combine in smem (same block), loss per point, block reduce,
// last-block-done final (fixed-order, deterministic).
__global__ void __launch_bounds__(CMB_TPB)
nn_combine_final(float* __restrict__ out)
{
    __shared__ float4 sm[4][PG_PER_BLK];
    __shared__ float  red[PG_PER_BLK];
    __shared__ bool   is_last;

    const int tid  = threadIdx.x;
    const int pidx = tid & (PG_PER_BLK - 1);       // 0..31
    const int qrt  = tid >> 5;                     // 0..3 (8 splits each)
    const int pg   = blockIdx.x * PG_PER_BLK + pidx;

    const float4* pm4 = (const float4*)g_pmin;
    const size_t base = (size_t)(qrt * 8) * NPG + pg;

    // 8 independent loads into separate registers (forced MLP=8)
    const float4 v0 = pm4[base + 0 * NPG];
    const float4 v1 = pm4[base + 1 * NPG];
    const float4 v2 = pm4[base + 2 * NPG];
    const float4 v3 = pm4[base + 3 * NPG];
    const float4 v4 = pm4[base + 4 * NPG];
    const float4 v5 = pm4[base + 5 * NPG];
    const float4 v6 = pm4[base + 6 * NPG];
    const float4 v7 = pm4[base + 7 * NPG];
    sm[qrt][pidx] = fmin4(fmin4(fmin4(v0, v1), fmin4(v2, v3)),
                          fmin4(fmin4(v4, v5), fmin4(v6, v7)));
    __syncthreads();

    if (tid < PG_PER_BLK) {
        float4 m = fmin4(fmin4(sm[0][tid], sm[1][tid]),
                         fmin4(sm[2][tid], sm[3][tid]));
        float dx = sqrtf(fmaxf(m.x, 0.0f)) - TARGET_F;
        float dy = sqrtf(fmaxf(m.y, 0.0f)) - TARGET_F;
        float dz = sqrtf(fmaxf(m.z, 0.0f)) - TARGET_F;
        float dw = sqrtf(fmaxf(m.w, 0.0f)) - TARGET_F;
        red[tid] = (dx * dx + dy * dy) + (dz * dz + dw * dw);
    }
    __syncthreads();
    if (tid == 0) {
        float v = 0.0f;
        #pragma unroll
        for (int p = 0; p < PG_PER_BLK; ++p) v += red[p];
        g_partials[blockIdx.x] = v;
        __threadfence();
        is_last = (atomicAdd(&g_sync, 1u) == CMB_BLKS - 1);
    }
    __syncthreads();
    if (!is_last) return;
    __threadfence();

    // Last block: fixed-order deterministic sum of 256 partials
    float acc = g_partials[tid] + g_partials[tid + 128];
    __shared__ float fin[CMB_TPB];
    fin[tid] = acc;
    __syncthreads();
    #pragma unroll
    for (int st = CMB_TPB / 2; st > 0; st >>= 1) {
        if (tid < st) fin[tid] += fin[tid + st];
        __syncthreads();
    }
    if (tid == 0) {
        out[0] = fin[0] * (1.0f / (float)TOTPTS);
        g_sync = 0;   // reset for next replay
    }
}

extern "C" void kernel_launch(void* const* d_in, const int* in_sizes, int n_in,
                              void* d_out, int out_size)
{
    const float* centers = (const float*)d_in[0];
    float* out = (float*)d_out;

    nn_min_kernel<<<NBLK_MIN, TPB>>>(centers);
    nn_combine_final<<<CMB_BLKS, CMB_TPB>>>(out);
}

// round 17
// speedup vs baseline: 1.3357x; 1.3357x over previous
#include <cuda_runtime.h>
#include <math_constants.h>

// Problem constants (fixed: centers [8, 4096, 3] fp32)
#define BATCH    8
#define NPTS     4096
#define TOTPTS   (BATCH * NPTS)       // 32768
#define TPB      128                  // threads per block
#define IPT      4                    // i-points per thread
#define ITILE    (TPB * IPT)          // 512 i per block
#define NITILES  (NPTS / ITILE)       // 8
#define SSPLIT   64                   // j-splits (= blocks per group)
#define JT       (NPTS / SSPLIT)      // 64 j per block
#define NBLK_MIN (BATCH * NITILES * SSPLIT)   // 4096
#define NGRP     (BATCH * NITILES)    // 64 groups (one per (batch, i-tile))
#define NPG4     (TOTPTS / 4)         // 8192 float4 point-groups
#define TARGET_F 0.2f

// Scratch (static device globals — no allocation allowed).
// Partial mins in [split][point] layout: coalesced store AND float4 load. 8 MB.
// Fully overwritten every call -> no reset needed.
__device__ float g_pmin[SSPLIT * TOTPTS];
__device__ float g_gpart[NGRP];           // per-group loss partials
__device__ unsigned int g_gcnt[NGRP];     // per-group arrival counters (self-reset)
__device__ unsigned int g_sync;           // group-completion counter (self-reset)

// ---- packed f32x2 helpers (FFMA2: only reachable via PTX) ----
__device__ __forceinline__ unsigned long long pack2(float a, float b) {
    unsigned long long r;
    asm("mov.b64 %0, {%1, %2};" : "=l"(r) : "f"(a), "f"(b));
    return r;
}
__device__ __forceinline__ unsigned long long fma2(unsigned long long a,
                                                   unsigned long long b,
                                                   unsigned long long c) {
    unsigned long long d;
    asm("fma.rn.f32x2 %0, %1, %2, %3;" : "=l"(d) : "l"(a), "l"(b), "l"(c));
    return d;
}
__device__ __forceinline__ float2 unpack2(unsigned long long v) {
    float2 f;
    asm("mov.b64 {%0, %1}, %2;" : "=f"(f.x), "=f"(f.y) : "l"(v));
    return f;
}
__device__ __forceinline__ float4 fmin4(float4 a, float4 b) {
    return make_float4(fminf(a.x, b.x), fminf(a.y, b.y),
                       fminf(a.z, b.z), fminf(a.w, b.w));
}

__global__ void __launch_bounds__(TPB)
nn_fused_kernel(const float* __restrict__ centers, float* __restrict__ out)
{
    // SoA j-tile: LDS.128 per array yields pre-packed {j,j+1} f32x2 lanes
    __shared__ __align__(16) float spx[JT], spy[JT], spz[JT], spw[JT];
    __shared__ float red[TPB];
    __shared__ unsigned int s_old, s_old2;

    const int blk = blockIdx.x;
    const int s   = blk & (SSPLIT - 1);            // j-split      0..63
    const int it  = (blk >> 6) & (NITILES - 1);    // i-tile       0..7
    const int b   = blk >> 9;                      // batch        0..7
    const int grp = blk >> 6;                      // group = b*NITILES + it
    const int tid = threadIdx.x;

    const float* cb = centers + (size_t)b * NPTS * 3;
    const int j_lo  = s  * JT;
    const int i_lo  = it * ITILE;

    // Stage j-tile (64 points)
    for (int p = tid; p < JT; p += TPB) {
        float x = cb[3 * (j_lo + p) + 0];
        float y = cb[3 * (j_lo + p) + 1];
        float z = cb[3 * (j_lo + p) + 2];
        spx[p] = x; spy[p] = y; spz[p] = z;
        spw[p] = fmaf(x, x, fmaf(y, y, z * z));
    }

    // i-constants, pre-packed {c,c} once
    unsigned long long ax2[IPT], ay2[IPT], az2[IPT];
    float sqi[IPT], tminA[IPT], tminB[IPT];
    int   msel[IPT];   // local j index equal to this i (may be out of range)
    #pragma unroll
    for (int k = 0; k < IPT; ++k) {
        const int gi = i_lo + tid + k * TPB;
        float x = cb[3 * gi + 0];
        float y = cb[3 * gi + 1];
        float z = cb[3 * gi + 2];
        ax2[k] = pack2(-2.0f * x, -2.0f * x);
        ay2[k] = pack2(-2.0f * y, -2.0f * y);
        az2[k] = pack2(-2.0f * z, -2.0f * z);
        sqi[k] = fmaf(x, x, fmaf(y, y, z * z));
        tminA[k] = CUDART_INF_F;
        tminB[k] = CUDART_INF_F;
        msel[k] = gi - j_lo;
    }
    __syncthreads();

    const ulonglong2* px2 = (const ulonglong2*)spx;
    const ulonglong2* py2 = (const ulonglong2*)spy;
    const ulonglong2* pz2 = (const ulonglong2*)spz;
    const ulonglong2* pw2 = (const ulonglong2*)spw;

    if ((s >> 3) != it) {
        // Off-diagonal block: clean fully-unrolled loop, no compares
        #pragma unroll
        for (int q = 0; q < JT / 4; ++q) {
            const ulonglong2 px = px2[q], py = py2[q], pz = pz2[q], pw = pw2[q];
            #pragma unroll
            for (int k = 0; k < IPT; ++k) {
                unsigned long long t0 = fma2(pz.x, az2[k], pw.x);
                t0 = fma2(py.x, ay2[k], t0);
                t0 = fma2(px.x, ax2[k], t0);
                unsigned long long t1 = fma2(pz.y, az2[k], pw.y);
                t1 = fma2(py.y, ay2[k], t1);
                t1 = fma2(px.y, ax2[k], t1);
                float2 a = unpack2(t0), c = unpack2(t1);
                tminA[k] = fminf(tminA[k], fminf(a.x, a.y));
                tminB[k] = fminf(tminB[k], fminf(c.x, c.y));
            }
        }
    } else {
        // Diagonal block (1/8 of blocks): predicate out j == i
        #pragma unroll
        for (int q = 0; q < JT / 4; ++q) {
            const int jb = q * 4;
            const ulonglong2 px = px2[q], py = py2[q], pz = pz2[q], pw = pw2[q];
            #pragma unroll
            for (int k = 0; k < IPT; ++k) {
                unsigned long long t0 = fma2(pz.x, az2[k], pw.x);
                t0 = fma2(py.x, ay2[k], t0);
                t0 = fma2(px.x, ax2[k], t0);
                unsigned long long t1 = fma2(pz.y, az2[k], pw.y);
                t1 = fma2(py.y, ay2[k], t1);
                t1 = fma2(px.y, ax2[k], t1);
                float2 a = unpack2(t0), c = unpack2(t1);
                const int m = msel[k];
                a.x = (jb + 0 == m) ? CUDART_INF_F : a.x;
                a.y = (jb + 1 == m) ? CUDART_INF_F : a.y;
                c.x = (jb + 2 == m) ? CUDART_INF_F : c.x;
                c.y = (jb + 3 == m) ? CUDART_INF_F : c.y;
                tminA[k] = fminf(tminA[k], fminf(a.x, a.y));
                tminB[k] = fminf(tminB[k], fminf(c.x, c.y));
            }
        }
    }

    // Coalesced partial store: pm[s][point]  (plain STG, no atomics)
    float* pm = g_pmin + (size_t)s * TOTPTS + b * NPTS + i_lo + tid;
    #pragma unroll
    for (int k = 0; k < IPT; ++k)
        pm[k * TPB] = sqi[k] + fminf(tminA[k], tminB[k]);

    // ---- hierarchical last-block-done (all fences: 1 thread/block, STG-only) ----
    __syncthreads();    // all warps' STGs ordered before tid0's release fence
    if (tid == 0) {
        __threadfence();                               // release this block's STGs
        s_old = atomicAdd(&g_gcnt[grp], 1u);
    }
    __syncthreads();
    if (s_old != SSPLIT - 1) return;                   // not the group's last block

    // Group combiner: this group's 64 splits are all complete.
    if (tid == 0) __threadfence();                     // acquire peers' STGs
    __syncthreads();

    // 512 points x 64 splits = 128 KB. Thread <-> one float4 point-group,
    // 64 loads batched x8 into separate registers (forced MLP=8).
    const float4* pm4 = (const float4*)g_pmin;
    const int pg = ((b * NPTS + i_lo) >> 2) + tid;
    float4 m = make_float4(CUDART_INF_F, CUDART_INF_F, CUDART_INF_F, CUDART_INF_F);
    #pragma unroll
    for (int so = 0; so < SSPLIT; so += 8) {
        const float4 v0 = pm4[(size_t)(so + 0) * NPG4 + pg];
        const float4 v1 = pm4[(size_t)(so + 1) * NPG4 + pg];
        const float4 v2 = pm4[(size_t)(so + 2) * NPG4 + pg];
        const float4 v3 = pm4[(size_t)(so + 3) * NPG4 + pg];
        const float4 v4 = pm4[(size_t)(so + 4) * NPG4 + pg];
        const float4 v5 = pm4[(size_t)(so + 5) * NPG4 + pg];
        const float4 v6 = pm4[(size_t)(so + 6) * NPG4 + pg];
        const float4 v7 = pm4[(size_t)(so + 7) * NPG4 + pg];
        m = fmin4(m, fmin4(fmin4(fmin4(v0, v1), fmin4(v2, v3)),
                           fmin4(fmin4(v4, v5), fmin4(v6, v7))));
    }
    {
        float dx = sqrtf(fmaxf(m.x, 0.0f)) - TARGET_F;   // clamp like reference
        float dy = sqrtf(fmaxf(m.y, 0.0f)) - TARGET_F;
        float dz = sqrtf(fmaxf(m.z, 0.0f)) - TARGET_F;
        float dw = sqrtf(fmaxf(m.w, 0.0f)) - TARGET_F;
        red[tid] = (dx * dx + dy * dy) + (dz * dz + dw * dw);
    }
    __syncthreads();
    #pragma unroll
    for (int st = TPB / 2; st > 0; st >>= 1) {
        if (tid < st) red[tid] += red[tid + st];
        __syncthreads();
    }
    if (tid == 0) {
        g_gpart[grp] = red[0];
        g_gcnt[grp] = 0u;                              // reset for next replay
        __threadfence();                               // release group partial
        s_old2 = atomicAdd(&g_sync, 1u);
    }
    __syncthreads();
    if (s_old2 != NGRP - 1) return;                    // not the last group

    // Final: fixed-order deterministic sum of 64 group partials.
    if (tid == 0) __threadfence();                     // acquire group partials
    __syncthreads();
    red[tid] = (tid < NGRP) ? g_gpart[tid] : 0.0f;
    __syncthreads();
    #pragma unroll
    for (int st = TPB / 2; st > 0; st >>= 1) {
        if (tid < st) red[tid] += red[tid + st];
        __syncthreads();
    }
    if (tid == 0) {
        out[0] = red[0] * (1.0f / (float)TOTPTS);
        g_sync = 0u;                                   // reset for next replay
    }
}

extern "C" void kernel_launch(void* const* d_in, const int* in_sizes, int n_in,
                              void* d_out, int out_size)
{
    const float* centers = (const float*)d_in[0];
    float* out = (float*)d_out;

    nn_fused_kernel<<<NBLK_MIN, TPB>>>(centers, out);
}